// round 3
// baseline (speedup 1.0000x reference)
#include <cuda_runtime.h>
#include <cstdint>

// CrfHead: out[b,t,:] = x[b,t,:] + transitions[argmax(x[b,t,:]), :]
// B=128, T=1024, TAGS=256  -> 131072 rows of 256 floats.
// One warp per row. Single pass: row stays in registers between argmax and add.

#define TAGS 256
#define ROWS (128 * 1024)
#define WARPS_PER_BLOCK 8
#define THREADS (WARPS_PER_BLOCK * 32)

__global__ __launch_bounds__(THREADS, 8)
void crf_head_kernel(const float4* __restrict__ x,
                     const float* __restrict__ trans,
                     float4* __restrict__ out) {
    const int warp_global = (blockIdx.x * THREADS + threadIdx.x) >> 5;
    const int lane = threadIdx.x & 31;
    if (warp_global >= ROWS) return;

    // Row = 256 floats = 64 float4. Lane l owns float4[l] and float4[l+32].
    const size_t base = (size_t)warp_global * (TAGS / 4);
    const float4 a = x[base + lane];
    const float4 b = x[base + lane + 32];

    // Local argmax over 8 elements; tie-break = lowest index (jnp.argmax semantics).
    float v = a.x;
    int idx = lane * 4;
    {
        const int i0 = lane * 4;
        if (a.y > v) { v = a.y; idx = i0 + 1; }
        if (a.z > v) { v = a.z; idx = i0 + 2; }
        if (a.w > v) { v = a.w; idx = i0 + 3; }
        const int i1 = (lane + 32) * 4;
        if (b.x > v) { v = b.x; idx = i1; }
        if (b.y > v) { v = b.y; idx = i1 + 1; }
        if (b.z > v) { v = b.z; idx = i1 + 2; }
        if (b.w > v) { v = b.w; idx = i1 + 3; }
    }

    // Warp argmax reduction; on equal value keep lower index (first occurrence).
    #pragma unroll
    for (int off = 16; off > 0; off >>= 1) {
        const float ov = __shfl_down_sync(0xFFFFFFFFu, v, off);
        const int   oi = __shfl_down_sync(0xFFFFFFFFu, idx, off);
        if (ov > v || (ov == v && oi < idx)) { v = ov; idx = oi; }
    }
    idx = __shfl_sync(0xFFFFFFFFu, idx, 0);

    // transitions row: 1KB, L2-resident (256KB total working set).
    const float4* trow = reinterpret_cast<const float4*>(trans + (size_t)idx * TAGS);
    const float4 t0 = __ldg(&trow[lane]);
    const float4 t1 = __ldg(&trow[lane + 32]);

    float4 r0, r1;
    r0.x = a.x + t0.x; r0.y = a.y + t0.y; r0.z = a.z + t0.z; r0.w = a.w + t0.w;
    r1.x = b.x + t1.x; r1.y = b.y + t1.y; r1.z = b.z + t1.z; r1.w = b.w + t1.w;

    out[base + lane]      = r0;
    out[base + lane + 32] = r1;
}

extern "C" void kernel_launch(void* const* d_in, const int* in_sizes, int n_in,
                              void* d_out, int out_size) {
    const float4* x     = reinterpret_cast<const float4*>(d_in[0]);
    const float*  trans = reinterpret_cast<const float*>(d_in[1]);
    float4*       out   = reinterpret_cast<float4*>(d_out);

    const int blocks = ROWS / WARPS_PER_BLOCK;  // 16384
    crf_head_kernel<<<blocks, THREADS>>>(x, trans, out);
}

// round 4
// speedup vs baseline: 1.0007x; 1.0007x over previous
#include <cuda_runtime.h>
#include <cstdint>

// CrfHead: out[b,t,:] = x[b,t,:] + transitions[argmax(x[b,t,:]), :]
// 131072 rows of 256 floats. One warp handles 2 rows (MLP=4 front-batched
// 128B loads). Argmax via order-preserving uint + REDUX.MAX, then REDUX.MIN
// on the candidate index for exact first-occurrence tie-break.

#define TAGS 256
#define ROWS (128 * 1024)
#define THREADS 256
#define WARPS_PER_BLOCK (THREADS / 32)
#define ROWS_PER_WARP 2
#define ROWS_PER_BLOCK (WARPS_PER_BLOCK * ROWS_PER_WARP)

// Monotone float -> uint32 map (total order matches float <, no NaNs in input).
__device__ __forceinline__ unsigned ford(float f) {
    unsigned u = __float_as_uint(f);
    return (u >> 31) ? ~u : (u | 0x80000000u);
}

// Local argmax over this lane's 8 elements; strict > keeps lowest index.
__device__ __forceinline__ void lane_argmax(const float4 a, const float4 b,
                                            int lane, float& v, int& idx) {
    const int i0 = lane * 4;
    const int i1 = (lane + 32) * 4;
    v = a.x; idx = i0;
    if (a.y > v) { v = a.y; idx = i0 + 1; }
    if (a.z > v) { v = a.z; idx = i0 + 2; }
    if (a.w > v) { v = a.w; idx = i0 + 3; }
    if (b.x > v) { v = b.x; idx = i1;     }
    if (b.y > v) { v = b.y; idx = i1 + 1; }
    if (b.z > v) { v = b.z; idx = i1 + 2; }
    if (b.w > v) { v = b.w; idx = i1 + 3; }
}

__device__ __forceinline__ int warp_argmax(float v, int idx) {
    const unsigned k = ford(v);
    const unsigned m = __reduce_max_sync(0xFFFFFFFFu, k);
    const unsigned cand = (k == m) ? (unsigned)idx : 0xFFFFu;
    return (int)__reduce_min_sync(0xFFFFFFFFu, cand);
}

__global__ __launch_bounds__(THREADS)
void crf_head_kernel(const float4* __restrict__ x,
                     const float* __restrict__ trans,
                     float4* __restrict__ out) {
    const int warp = (blockIdx.x * THREADS + threadIdx.x) >> 5;
    const int lane = threadIdx.x & 31;

    const int row0 = warp * ROWS_PER_WARP;
    if (row0 >= ROWS) return;

    const size_t base0 = (size_t)row0 * (TAGS / 4);
    const size_t base1 = base0 + (TAGS / 4);

    // Front-batch 4 independent 128B loads (MLP=4).
    const float4 a0 = __ldcs(&x[base0 + lane]);
    const float4 b0 = __ldcs(&x[base0 + lane + 32]);
    const float4 a1 = __ldcs(&x[base1 + lane]);
    const float4 b1 = __ldcs(&x[base1 + lane + 32]);

    float v0, v1; int i0, i1;
    lane_argmax(a0, b0, lane, v0, i0);
    lane_argmax(a1, b1, lane, v1, i1);

    const int best0 = warp_argmax(v0, i0);
    const int best1 = warp_argmax(v1, i1);

    // transitions rows: 256KB total working set, L2-resident.
    const float4* t0p = reinterpret_cast<const float4*>(trans + (size_t)best0 * TAGS);
    const float4* t1p = reinterpret_cast<const float4*>(trans + (size_t)best1 * TAGS);
    const float4 ta0 = __ldg(&t0p[lane]);
    const float4 tb0 = __ldg(&t0p[lane + 32]);
    const float4 ta1 = __ldg(&t1p[lane]);
    const float4 tb1 = __ldg(&t1p[lane + 32]);

    float4 r;
    r.x = a0.x + ta0.x; r.y = a0.y + ta0.y; r.z = a0.z + ta0.z; r.w = a0.w + ta0.w;
    __stcs(&out[base0 + lane], r);
    r.x = b0.x + tb0.x; r.y = b0.y + tb0.y; r.z = b0.z + tb0.z; r.w = b0.w + tb0.w;
    __stcs(&out[base0 + lane + 32], r);
    r.x = a1.x + ta1.x; r.y = a1.y + ta1.y; r.z = a1.z + ta1.z; r.w = a1.w + ta1.w;
    __stcs(&out[base1 + lane], r);
    r.x = b1.x + tb1.x; r.y = b1.y + tb1.y; r.z = b1.z + tb1.z; r.w = b1.w + tb1.w;
    __stcs(&out[base1 + lane + 32], r);
}

extern "C" void kernel_launch(void* const* d_in, const int* in_sizes, int n_in,
                              void* d_out, int out_size) {
    const float4* x     = reinterpret_cast<const float4*>(d_in[0]);
    const float*  trans = reinterpret_cast<const float*>(d_in[1]);
    float4*       out   = reinterpret_cast<float4*>(d_out);

    const int blocks = ROWS / ROWS_PER_BLOCK;  // 8192
    crf_head_kernel<<<blocks, THREADS>>>(x, trans, out);
}